// round 1
// baseline (speedup 1.0000x reference)
#include <cuda_runtime.h>
#include <cstdint>

#define NPTS   200000
#define CIN    64
#define COUT   16
#define SXD    998
#define SYD    998
#define SZD    38
#define YZ     37924          /* SYD*SZD */
#define SENTV  37848152u      /* SXD*SYD*SZD */
#define NKTOT  5400000        /* NPTS*27 */
#define WORDS  1182755        /* ceil(SENTV/32) */
#define CHUNK  4096
#define NPART  289            /* ceil(WORDS/CHUNK) */
#define WPAD   (NPART*CHUNK)  /* 1183744 */

// ---------------- device scratch (static: allowed) ----------------
__device__ __align__(16) unsigned g_bitmap[WPAD];
__device__ __align__(16) unsigned g_pref[WPAD];
__device__ unsigned g_part[NPART];
__device__ unsigned g_M;

// ---------------- kernels ----------------
__global__ void k_zero() {
    unsigned i = blockIdx.x * blockDim.x + threadIdx.x;
    if (i < WPAD) g_bitmap[i] = 0u;
}

__global__ void k_mark(const int4* __restrict__ coords) {
    int n = blockIdx.x * blockDim.x + threadIdx.x;
    if (n >= NPTS) return;
    int4 c = coords[n];
    int x = c.y, y = c.z, z = c.w;
#pragma unroll
    for (int k = 0; k < 27; k++) {
        int ox = x - k / 9;
        int oy = y - (k / 3) % 3;
        int oz = z - k % 3;
        if ((unsigned)ox < SXD && (unsigned)oy < SYD && (unsigned)oz < SZD) {
            unsigned lin = (unsigned)ox * YZ + (unsigned)oy * SZD + (unsigned)oz;
            atomicOr(&g_bitmap[lin >> 5], 1u << (lin & 31));
        }
    }
}

// per-chunk popcount sums
__global__ void k_scan1() {
    __shared__ unsigned sh[256];
    unsigned base = blockIdx.x * CHUNK + threadIdx.x * 16;
    unsigned s = 0;
#pragma unroll
    for (int i = 0; i < 16; i += 4) {
        uint4 v = *reinterpret_cast<const uint4*>(&g_bitmap[base + i]);
        s += __popc(v.x) + __popc(v.y) + __popc(v.z) + __popc(v.w);
    }
    sh[threadIdx.x] = s;
    __syncthreads();
    for (int off = 128; off > 0; off >>= 1) {
        if (threadIdx.x < (unsigned)off) sh[threadIdx.x] += sh[threadIdx.x + off];
        __syncthreads();
    }
    if (threadIdx.x == 0) g_part[blockIdx.x] = sh[0];
}

// exclusive scan of partials (single block), total -> g_M
__global__ void k_scan2() {
    __shared__ unsigned sh[512];
    unsigned t = threadIdx.x;
    unsigned v = (t < NPART) ? g_part[t] : 0u;
    sh[t] = v;
    __syncthreads();
    for (int off = 1; off < 512; off <<= 1) {
        unsigned add = (t >= (unsigned)off) ? sh[t - off] : 0u;
        __syncthreads();
        sh[t] += add;
        __syncthreads();
    }
    if (t < NPART) g_part[t] = sh[t] - v;
    if (t == NPART - 1) g_M = sh[t];
}

// per-word exclusive prefix of popcounts
__global__ void k_scan3() {
    __shared__ unsigned sh[256];
    unsigned base = blockIdx.x * CHUNK + threadIdx.x * 16;
    unsigned w[16];
#pragma unroll
    for (int i = 0; i < 16; i += 4)
        *reinterpret_cast<uint4*>(&w[i]) = *reinterpret_cast<const uint4*>(&g_bitmap[base + i]);
    unsigned s = 0;
#pragma unroll
    for (int i = 0; i < 16; i++) s += __popc(w[i]);
    sh[threadIdx.x] = s;
    __syncthreads();
    for (int off = 1; off < 256; off <<= 1) {
        unsigned add = (threadIdx.x >= (unsigned)off) ? sh[threadIdx.x - off] : 0u;
        __syncthreads();
        sh[threadIdx.x] += add;
        __syncthreads();
    }
    unsigned run = g_part[blockIdx.x] + (sh[threadIdx.x] - s);
#pragma unroll
    for (int i = 0; i < 16; i++) {
        g_pref[base + i] = run;
        run += __popc(w[i]);
    }
}

// write uniq values (sorted) for occupied cells
__global__ void k_emit(float* __restrict__ uniqf) {
    unsigned i = blockIdx.x * blockDim.x + threadIdx.x;
    if (i >= WORDS) return;
    unsigned bits = g_bitmap[i];
    if (!bits) return;
    unsigned r = g_pref[i];
    unsigned vbase = i << 5;
    while (bits) {
        unsigned b = __ffs(bits) - 1u;
        bits &= bits - 1u;
        uniqf[r++] = (float)(vbase + b);
    }
}

// init out rows: bias for j<M, zeros for j>=M  (coalesced float4)
__global__ void k_fillout(float4* __restrict__ out4, const float4* __restrict__ bias4) {
    unsigned i = blockIdx.x * blockDim.x + threadIdx.x;
    if (i >= (unsigned)NKTOT * 4u) return;
    unsigned j = i >> 2;
    unsigned M = g_M;
    float4 v;
    if (j < M) v = bias4[i & 3u];
    else       v = make_float4(0.f, 0.f, 0.f, 0.f);
    out4[i] = v;
}

// uniq padding with SENT for j>=M
__global__ void k_filluniq(float* __restrict__ uniqf) {
    unsigned j = blockIdx.x * blockDim.x + threadIdx.x;
    if (j >= (unsigned)NKTOT) return;
    if (j >= g_M) uniqf[j] = 37848152.0f;
}

// main compute+scatter: warp = 8 points x 4 output-groups, loop 27 offsets
__global__ void __launch_bounds__(256) k_scatter(
    const float4* __restrict__ feats4, const int4* __restrict__ coords,
    const float4* __restrict__ W4, float* __restrict__ out)
{
    int gtid = blockIdx.x * blockDim.x + threadIdx.x;
    int warp = gtid >> 5;
    int lane = threadIdx.x & 31;
    int p = lane >> 2;          // 0..7: point within warp
    int g = lane & 3;           // 0..3: output quad (o = 4g..4g+3)
    int n = warp * 8 + p;
    bool pv = (n < NPTS);
    int nn = pv ? n : 0;
    int4 cc = coords[nn];

    // preload this point's 64 features into registers
    float4 fq[16];
#pragma unroll
    for (int i = 0; i < 16; i++) fq[i] = __ldg(&feats4[(size_t)nn * 16 + i]);
    const float* fs = reinterpret_cast<const float*>(fq);

#pragma unroll 1
    for (int k = 0; k < 27; k++) {
        int ox = cc.y - k / 9;
        int oy = cc.z - (k / 3) % 3;
        int oz = cc.w - k % 3;
        bool valid = pv && (unsigned)ox < SXD && (unsigned)oy < SYD && (unsigned)oz < SZD;

        unsigned rank = 0u;
        if (g == 0 && valid) {
            unsigned lin = (unsigned)ox * YZ + (unsigned)oy * SZD + (unsigned)oz;
            unsigned word = lin >> 5;
            rank = __ldg(&g_pref[word]) +
                   __popc(__ldg(&g_bitmap[word]) & ((1u << (lin & 31)) - 1u));
        }
        rank = __shfl_sync(0xffffffffu, rank, lane & ~3);

        const float4* wk = W4 + k * 256 + g;   // W[k][c][4g..4g+3]
        float a0 = 0.f, a1 = 0.f, a2 = 0.f, a3 = 0.f;
#pragma unroll
        for (int c = 0; c < 64; c++) {
            float4 w4 = __ldg(&wk[c * 4]);
            float f = fs[c];
            a0 = fmaf(f, w4.x, a0);
            a1 = fmaf(f, w4.y, a1);
            a2 = fmaf(f, w4.z, a2);
            a3 = fmaf(f, w4.w, a3);
        }
        if (valid) {
            float* dst = out + (size_t)rank * 16 + g * 4;
            asm volatile("red.global.add.v4.f32 [%0], {%1,%2,%3,%4};"
                         :: "l"(dst), "f"(a0), "f"(a1), "f"(a2), "f"(a3)
                         : "memory");
        }
    }
}

// ---------------- launch ----------------
extern "C" void kernel_launch(void* const* d_in, const int* in_sizes, int n_in,
                              void* d_out, int out_size) {
    const float* feats = (const float*)d_in[0];
    const int*   coords = (const int*)d_in[1];
    const float* W = (const float*)d_in[2];
    const float* bias = (const float*)d_in[3];
    float* out = (float*)d_out;
    float* uniqf = out + (size_t)NKTOT * 16;
    bool has_uniq = (out_size >= NKTOT * 17);

    k_zero<<<(WPAD + 255) / 256, 256>>>();
    k_mark<<<(NPTS + 255) / 256, 256>>>((const int4*)coords);
    k_scan1<<<NPART, 256>>>();
    k_scan2<<<1, 512>>>();
    k_scan3<<<NPART, 256>>>();
    if (has_uniq) {
        k_emit<<<(WORDS + 255) / 256, 256>>>(uniqf);
        k_filluniq<<<(NKTOT + 255) / 256, 256>>>(uniqf);
    }
    k_fillout<<<(NKTOT * 4 + 255) / 256, 256>>>((float4*)out, (const float4*)bias);

    int warps = (NPTS + 7) / 8;                 // 25000
    int blocks = (warps + 7) / 8;               // 3125 blocks of 8 warps
    k_scatter<<<blocks, 256>>>((const float4*)feats, (const int4*)coords,
                               (const float4*)W, out);
}